// round 1
// baseline (speedup 1.0000x reference)
#include <cuda_runtime.h>
#include <math.h>

// Problem dims (fixed by dataset)
#define Bc 8
#define Sc 4096
#define Tc 512
#define Dc 1024
#define NEG_NUM -10000.0f

// GEMM tiling
#define BM 128
#define BN 128
#define BK 16
#define TM 8
#define TN 8
#define SSTRIDE 132   // padded smem row stride (floats), multiple of 4 for float4

// Fallback scratch for p_ctx if the harness only wants expected_ctx
__device__ float g_p_scratch[(size_t)Bc * Tc * Sc];

// ---------------------------------------------------------------------------
// Kernel 1: scores[b,t,s] = (sum_d Q[b,t,d] * C[b,s,d]) / 32, masked
// Writes into P (the p_ctx buffer), fp32.
// ---------------------------------------------------------------------------
__global__ __launch_bounds__(256) void qk_kernel(
    const float* __restrict__ Q, const float* __restrict__ C,
    const int* __restrict__ mask, float* __restrict__ P)
{
    __shared__ float sA[BK][SSTRIDE];   // Q^T tile: [k][m]
    __shared__ float sB[BK][SSTRIDE];   // C^T tile: [k][n]

    const int b  = blockIdx.z;
    const int m0 = blockIdx.y * BM;     // t tile
    const int n0 = blockIdx.x * BN;     // s tile
    const float* Qb = Q + (size_t)b * Tc * Dc;
    const float* Cb = C + (size_t)b * Sc * Dc;

    const int tid = threadIdx.x;
    const int tx = tid & 15;
    const int ty = tid >> 4;

    float acc[TM][TN];
#pragma unroll
    for (int i = 0; i < TM; i++)
#pragma unroll
        for (int j = 0; j < TN; j++) acc[i][j] = 0.0f;

    for (int k0 = 0; k0 < Dc; k0 += BK) {
        // Load A (Q) tile 128x16 and B (C) tile 128x16, both transposed into smem
#pragma unroll
        for (int ld = 0; ld < 2; ld++) {
            int idx = tid + ld * 256;        // 0..511
            int row = idx >> 2;              // 0..127
            int kc  = (idx & 3) << 2;        // 0,4,8,12
            float4 va = *(const float4*)(Qb + (size_t)(m0 + row) * Dc + k0 + kc);
            sA[kc + 0][row] = va.x; sA[kc + 1][row] = va.y;
            sA[kc + 2][row] = va.z; sA[kc + 3][row] = va.w;
            float4 vb = *(const float4*)(Cb + (size_t)(n0 + row) * Dc + k0 + kc);
            sB[kc + 0][row] = vb.x; sB[kc + 1][row] = vb.y;
            sB[kc + 2][row] = vb.z; sB[kc + 3][row] = vb.w;
        }
        __syncthreads();

#pragma unroll
        for (int k = 0; k < BK; k++) {
            float4 a0 = *(const float4*)&sA[k][ty * TM];
            float4 a1 = *(const float4*)&sA[k][ty * TM + 4];
            float4 b0 = *(const float4*)&sB[k][tx * TN];
            float4 b1 = *(const float4*)&sB[k][tx * TN + 4];
            float a[TM] = {a0.x, a0.y, a0.z, a0.w, a1.x, a1.y, a1.z, a1.w};
            float bb[TN] = {b0.x, b0.y, b0.z, b0.w, b1.x, b1.y, b1.z, b1.w};
#pragma unroll
            for (int i = 0; i < TM; i++)
#pragma unroll
                for (int j = 0; j < TN; j++)
                    acc[i][j] = fmaf(a[i], bb[j], acc[i][j]);
        }
        __syncthreads();
    }

    // Epilogue: scale + mask, write fp32 scores
    const float scale = 0.03125f; // 1/sqrt(1024)
    float* Pb = P + (size_t)b * Tc * Sc;
    const int sbase = n0 + tx * TN;
    int msk[TN];
#pragma unroll
    for (int j = 0; j < TN; j++) msk[j] = mask[b * Sc + sbase + j];

#pragma unroll
    for (int i = 0; i < TM; i++) {
        int t = m0 + ty * TM + i;
        float* prow = Pb + (size_t)t * Sc + sbase;
        float4 v0, v1;
        v0.x = msk[0] ? acc[i][0] * scale : NEG_NUM;
        v0.y = msk[1] ? acc[i][1] * scale : NEG_NUM;
        v0.z = msk[2] ? acc[i][2] * scale : NEG_NUM;
        v0.w = msk[3] ? acc[i][3] * scale : NEG_NUM;
        v1.x = msk[4] ? acc[i][4] * scale : NEG_NUM;
        v1.y = msk[5] ? acc[i][5] * scale : NEG_NUM;
        v1.z = msk[6] ? acc[i][6] * scale : NEG_NUM;
        v1.w = msk[7] ? acc[i][7] * scale : NEG_NUM;
        *(float4*)(prow)     = v0;
        *(float4*)(prow + 4) = v1;
    }
}

// ---------------------------------------------------------------------------
// Kernel 2: in-place softmax over the last dim (S=4096) of P[b,t,:]
// One 256-thread block per (b,t) row; 16 elements per thread.
// ---------------------------------------------------------------------------
__global__ __launch_bounds__(256) void softmax_kernel(float* __restrict__ P)
{
    float* p = P + (size_t)blockIdx.x * Sc;
    const int tid  = threadIdx.x;
    const int warp = tid >> 5;
    const int lane = tid & 31;

    __shared__ float red_max[8];
    __shared__ float red_sum[8];

    float v[16];
    float m = -1e30f;
#pragma unroll
    for (int i = 0; i < 16; i++) {
        v[i] = p[i * 256 + tid];
        m = fmaxf(m, v[i]);
    }
#pragma unroll
    for (int off = 16; off > 0; off >>= 1)
        m = fmaxf(m, __shfl_xor_sync(0xffffffffu, m, off));
    if (lane == 0) red_max[warp] = m;
    __syncthreads();
    float bm = red_max[0];
#pragma unroll
    for (int w = 1; w < 8; w++) bm = fmaxf(bm, red_max[w]);

    float s = 0.0f;
#pragma unroll
    for (int i = 0; i < 16; i++) {
        v[i] = expf(v[i] - bm);
        s += v[i];
    }
#pragma unroll
    for (int off = 16; off > 0; off >>= 1)
        s += __shfl_xor_sync(0xffffffffu, s, off);
    if (lane == 0) red_sum[warp] = s;
    __syncthreads();
    float tot = 0.0f;
#pragma unroll
    for (int w = 0; w < 8; w++) tot += red_sum[w];
    float inv = 1.0f / tot;

#pragma unroll
    for (int i = 0; i < 16; i++)
        p[i * 256 + tid] = v[i] * inv;
}

// ---------------------------------------------------------------------------
// Kernel 3: expected[b,t,d] = sum_s P[b,t,s] * C[b,s,d]
// ---------------------------------------------------------------------------
__global__ __launch_bounds__(256) void pv_kernel(
    const float* __restrict__ P, const float* __restrict__ C,
    float* __restrict__ O)
{
    __shared__ float sA[BK][SSTRIDE];   // P^T tile: [k=s][m=t]
    __shared__ float sB[BK][SSTRIDE];   // C tile:   [k=s][n=d]

    const int b  = blockIdx.z;
    const int m0 = blockIdx.y * BM;     // t tile
    const int n0 = blockIdx.x * BN;     // d tile
    const float* Pb = P + (size_t)b * Tc * Sc;
    const float* Cb = C + (size_t)b * Sc * Dc;

    const int tid = threadIdx.x;
    const int tx = tid & 15;
    const int ty = tid >> 4;

    float acc[TM][TN];
#pragma unroll
    for (int i = 0; i < TM; i++)
#pragma unroll
        for (int j = 0; j < TN; j++) acc[i][j] = 0.0f;

    for (int k0 = 0; k0 < Sc; k0 += BK) {
        // A (P) tile 128x16, transposed store
#pragma unroll
        for (int ld = 0; ld < 2; ld++) {
            int idx = tid + ld * 256;
            int row = idx >> 2;
            int kc  = (idx & 3) << 2;
            float4 va = *(const float4*)(Pb + (size_t)(m0 + row) * Sc + k0 + kc);
            sA[kc + 0][row] = va.x; sA[kc + 1][row] = va.y;
            sA[kc + 2][row] = va.z; sA[kc + 3][row] = va.w;
        }
        // B (C) tile 16x128, direct store
#pragma unroll
        for (int ld = 0; ld < 2; ld++) {
            int idx  = tid + ld * 256;       // 0..511
            int krow = idx >> 5;             // 0..15
            int nc   = (idx & 31) << 2;      // 0..124
            float4 vb = *(const float4*)(Cb + (size_t)(k0 + krow) * Dc + n0 + nc);
            *(float4*)&sB[krow][nc] = vb;
        }
        __syncthreads();

#pragma unroll
        for (int k = 0; k < BK; k++) {
            float4 a0 = *(const float4*)&sA[k][ty * TM];
            float4 a1 = *(const float4*)&sA[k][ty * TM + 4];
            float4 b0 = *(const float4*)&sB[k][tx * TN];
            float4 b1 = *(const float4*)&sB[k][tx * TN + 4];
            float a[TM] = {a0.x, a0.y, a0.z, a0.w, a1.x, a1.y, a1.z, a1.w};
            float bb[TN] = {b0.x, b0.y, b0.z, b0.w, b1.x, b1.y, b1.z, b1.w};
#pragma unroll
            for (int i = 0; i < TM; i++)
#pragma unroll
                for (int j = 0; j < TN; j++)
                    acc[i][j] = fmaf(a[i], bb[j], acc[i][j]);
        }
        __syncthreads();
    }

    float* Ob = O + (size_t)b * Tc * Dc;
#pragma unroll
    for (int i = 0; i < TM; i++) {
        int t = m0 + ty * TM + i;
        float* orow = Ob + (size_t)t * Dc + n0 + tx * TN;
        float4 v0 = {acc[i][0], acc[i][1], acc[i][2], acc[i][3]};
        float4 v1 = {acc[i][4], acc[i][5], acc[i][6], acc[i][7]};
        *(float4*)(orow)     = v0;
        *(float4*)(orow + 4) = v1;
    }
}

// ---------------------------------------------------------------------------
// Launch: out = [expected_ctx (B*T*D) | p_ctx (B*T*S)]
// ---------------------------------------------------------------------------
extern "C" void kernel_launch(void* const* d_in, const int* in_sizes, int n_in,
                              void* d_out, int out_size)
{
    const float* ctx   = (const float*)d_in[0];
    const float* query = (const float*)d_in[1];
    const int*   mask  = (const int*)d_in[2];
    float* out = (float*)d_out;

    const size_t BTD = (size_t)Bc * Tc * Dc;   // 4,194,304
    const size_t BTS = (size_t)Bc * Tc * Sc;   // 16,777,216

    float* expected_out = out;
    float* p_out;
    if ((size_t)out_size >= BTD + BTS) {
        p_out = out + BTD;
    } else {
        // Harness only wants expected_ctx; use device-global scratch for P.
        void* sp = nullptr;
        cudaGetSymbolAddress(&sp, g_p_scratch);
        p_out = (float*)sp;
    }

    dim3 blk(256);
    dim3 g1(Sc / BN, Tc / BM, Bc);   // 32 x 4 x 8
    qk_kernel<<<g1, blk>>>(query, ctx, mask, p_out);

    softmax_kernel<<<Bc * Tc, blk>>>(p_out);

    dim3 g2(Dc / BN, Tc / BM, Bc);   // 8 x 4 x 8
    pv_kernel<<<g2, blk>>>(p_out, ctx, expected_out);
}

// round 5
// speedup vs baseline: 2.4404x; 2.4404x over previous
#include <cuda_runtime.h>
#include <cuda_bf16.h>
#include <math.h>
#include <stdint.h>

// Problem dims (fixed by dataset)
#define Bc 8
#define Sc 4096
#define Tc 512
#define Dc 1024
#define NEG_NUM -10000.0f

// ---------------------------------------------------------------------------
// Scratch (device globals; no allocations allowed)
// ---------------------------------------------------------------------------
__device__ __nv_bfloat16 g_Chi [(size_t)Bc * Sc * Dc];
__device__ __nv_bfloat16 g_Clo [(size_t)Bc * Sc * Dc];
__device__ __nv_bfloat16 g_Cthi[(size_t)Bc * Dc * Sc];
__device__ __nv_bfloat16 g_Ctlo[(size_t)Bc * Dc * Sc];
__device__ __nv_bfloat16 g_Qhi [(size_t)Bc * Tc * Dc];
__device__ __nv_bfloat16 g_Qlo [(size_t)Bc * Tc * Dc];
__device__ __nv_bfloat16 g_Phi [(size_t)Bc * Tc * Sc];
__device__ __nv_bfloat16 g_Plo [(size_t)Bc * Tc * Sc];
__device__ float         g_p_scratch[(size_t)Bc * Tc * Sc];

// ---------------------------------------------------------------------------
// PTX helpers (baseline PTX only: cp.async, ldmatrix, mma.sync)
// ---------------------------------------------------------------------------
__device__ __forceinline__ uint32_t smem_u32(const void* p) {
    uint32_t a;
    asm("{ .reg .u64 t; cvta.to.shared.u64 t, %1; cvt.u32.u64 %0, t; }" : "=r"(a) : "l"(p));
    return a;
}

__device__ __forceinline__ void cp_async16(uint32_t dst, const void* src) {
    asm volatile("cp.async.cg.shared.global [%0], [%1], 16;" :: "r"(dst), "l"(src));
}
#define CP_COMMIT() asm volatile("cp.async.commit_group;" ::: "memory")
#define CP_WAIT2()  asm volatile("cp.async.wait_group 2;"  ::: "memory")

__device__ __forceinline__ void ldsm_x4(uint32_t* r, uint32_t addr) {
    asm volatile("ldmatrix.sync.aligned.m8n8.x4.shared.b16 {%0,%1,%2,%3}, [%4];"
                 : "=r"(r[0]), "=r"(r[1]), "=r"(r[2]), "=r"(r[3]) : "r"(addr));
}
__device__ __forceinline__ void mma16816(float* d, const uint32_t* a, uint32_t b0, uint32_t b1) {
    asm volatile(
        "mma.sync.aligned.m16n8k16.row.col.f32.bf16.bf16.f32 "
        "{%0,%1,%2,%3}, {%4,%5,%6,%7}, {%8,%9}, {%0,%1,%2,%3};"
        : "+f"(d[0]), "+f"(d[1]), "+f"(d[2]), "+f"(d[3])
        : "r"(a[0]), "r"(a[1]), "r"(a[2]), "r"(a[3]), "r"(b0), "r"(b1));
}

// smem layout (dynamic): [0,512) mask | [1024, +3*64KB) stages
#define SM_MASK    0
#define SM_STAGE0  1024
#define TILE_BYTES_ 16384          // 128 rows x 128B (64 bf16)
#define STAGE_BYTES 65536          // Ahi, Alo, Bhi, Blo
#define SMEM_TOTAL (SM_STAGE0 + 3 * STAGE_BYTES)   // 197632

// SW128 swizzle restricted to our geometry: offset = r*128 + c (c < 128)
// -> swizzled = r*128 + (c ^ ((r & 7) << 4))

// ---------------------------------------------------------------------------
// bf16x3 split GEMM via mma.sync: D[m,n] = sum_k A[m,k]*B[n,k]
// CTA tile 128x128, 8 warps (2x4), warp tile 64x32, BK=64, 3-stage cp.async.
// ---------------------------------------------------------------------------
template <int KTOT, bool IS_QK>
__global__ __launch_bounds__(256, 1) void gemm_hmma(
    const __nv_bfloat16* __restrict__ Ahi, const __nv_bfloat16* __restrict__ Alo,
    const __nv_bfloat16* __restrict__ Bhi, const __nv_bfloat16* __restrict__ Blo,
    const int* __restrict__ mask, float* __restrict__ Out,
    int lda, int ldb, int ldo, size_t strA, size_t strB, size_t strO)
{
    extern __shared__ __align__(1024) char smem[];
    const uint32_t sb  = smem_u32(smem);
    const int tid  = threadIdx.x;
    const int lane = tid & 31;
    const int wid  = tid >> 5;
    const int wm   = wid & 1;        // 2 warp-rows of 64
    const int wn   = wid >> 1;       // 4 warp-cols of 32
    const int b    = blockIdx.z;
    const int n0   = blockIdx.x * 128;
    const int m0   = blockIdx.y * 128;
    constexpr int NST = KTOT / 64;

    int* smask = (int*)(smem + SM_MASK);
    if (IS_QK && tid < 128) smask[tid] = mask[b * Sc + n0 + tid];

    // ---- cp.async load geometry (16 loads / thread / stage) ----
    uint32_t swz[4];
    size_t   ga[4], gb[4];
#pragma unroll
    for (int j = 0; j < 4; j++) {
        int within = tid + 256 * j;
        int row = within >> 3;
        int u   = within & 7;
        uint32_t off = (uint32_t)(row * 128 + u * 16);
        swz[j] = off ^ ((off >> 3) & 0x70);
        ga[j]  = (size_t)(m0 + row) * lda + u * 8;
        gb[j]  = (size_t)(n0 + row) * ldb + u * 8;
    }
    const __nv_bfloat16* Ah = Ahi + (size_t)b * strA;
    const __nv_bfloat16* Al = Alo + (size_t)b * strA;
    const __nv_bfloat16* Bh = Bhi + (size_t)b * strB;
    const __nv_bfloat16* Bl = Blo + (size_t)b * strB;

    auto load_stage = [&](int k) {
        const uint32_t stg = sb + SM_STAGE0 + (k % 3) * STAGE_BYTES;
        const int kelt = k * 64;
#pragma unroll
        for (int j = 0; j < 4; j++) {
            cp_async16(stg + 0 * TILE_BYTES_ + swz[j], Ah + ga[j] + kelt);
            cp_async16(stg + 1 * TILE_BYTES_ + swz[j], Al + ga[j] + kelt);
            cp_async16(stg + 2 * TILE_BYTES_ + swz[j], Bh + gb[j] + kelt);
            cp_async16(stg + 3 * TILE_BYTES_ + swz[j], Bl + gb[j] + kelt);
        }
    };

    // ---- ldmatrix lane addressing (within-tile offsets) ----
    // A tiles: 16x16 at (wm*64 + mt*16, kk). lanes 0-15 -> rows, lanes 16-31
    // -> same rows, k-half +16B. Non-trans.
    uint32_t apart[4], aswz[4];
#pragma unroll
    for (int mt = 0; mt < 4; mt++) {
        int r = wm * 64 + mt * 16 + (lane & 15);
        apart[mt] = (uint32_t)r * 128;
        aswz[mt]  = (uint32_t)((r & 7) << 4);
    }
    const uint32_t acol = (uint32_t)((lane >> 4) * 16);
    // B tiles: n16 x k16 region per p; 4 matrices (n8 group j, k-half h),
    // NON-trans ldmatrix: B smem is [n][k] = K x N col-major as mma wants.
    // lane group g = lane>>3: j = g>>1 (n8 group), h = g&1 (k-half).
    uint32_t bpart[2], bswz[2];
    {
        int g  = lane >> 3;
        int lr = lane & 7;
        int j  = g >> 1;
#pragma unroll
        for (int p = 0; p < 2; p++) {
            int r = wn * 32 + p * 16 + j * 8 + lr;
            bpart[p] = (uint32_t)r * 128;
            bswz[p]  = (uint32_t)((r & 7) << 4);
        }
    }
    const uint32_t bcol = (uint32_t)((lane >> 3) & 1) * 16;

    float acc[4][4][4];
#pragma unroll
    for (int mt = 0; mt < 4; mt++)
#pragma unroll
        for (int nt = 0; nt < 4; nt++)
#pragma unroll
            for (int f = 0; f < 4; f++) acc[mt][nt][f] = 0.0f;

    // ---- pipeline ----
    load_stage(0); CP_COMMIT();
    load_stage(1); CP_COMMIT();

    for (int k = 0; k < NST; k++) {
        if (k + 2 < NST) load_stage(k + 2);
        CP_COMMIT();
        CP_WAIT2();            // stage k's group retired
        __syncthreads();       // visible to all warps; prev compute done

        const uint32_t stg = sb + SM_STAGE0 + (k % 3) * STAGE_BYTES;
#pragma unroll
        for (int kk = 0; kk < 64; kk += 16) {
            uint32_t ahi[4][4], alo[4][4], bhi[2][4], blo[2][4];
            const uint32_t ac = (uint32_t)(kk * 2) + acol;
            const uint32_t bc = (uint32_t)(kk * 2) + bcol;
#pragma unroll
            for (int mt = 0; mt < 4; mt++) {
                ldsm_x4(ahi[mt], stg + 0 * TILE_BYTES_ + apart[mt] + (ac ^ aswz[mt]));
                ldsm_x4(alo[mt], stg + 1 * TILE_BYTES_ + apart[mt] + (ac ^ aswz[mt]));
            }
#pragma unroll
            for (int p = 0; p < 2; p++) {
                ldsm_x4(bhi[p], stg + 2 * TILE_BYTES_ + bpart[p] + (bc ^ bswz[p]));
                ldsm_x4(blo[p], stg + 3 * TILE_BYTES_ + bpart[p] + (bc ^ bswz[p]));
            }
#pragma unroll
            for (int mt = 0; mt < 4; mt++)
#pragma unroll
                for (int nt = 0; nt < 4; nt++) {
                    const int p = nt >> 1, o = (nt & 1) * 2;
                    mma16816(acc[mt][nt], ahi[mt], bhi[p][o], bhi[p][o + 1]);
                    mma16816(acc[mt][nt], ahi[mt], blo[p][o], blo[p][o + 1]);
                    mma16816(acc[mt][nt], alo[mt], bhi[p][o], bhi[p][o + 1]);
                }
        }
        __syncthreads();       // all warps done reading stage k (buffer reuse)
    }

    // ---- epilogue ----
    const int r0 = lane >> 2;
    const int c0 = (lane & 3) * 2;
    float* Ob = Out + (size_t)b * strO;
#pragma unroll
    for (int mt = 0; mt < 4; mt++) {
        const int row = m0 + wm * 64 + mt * 16 + r0;
#pragma unroll
        for (int nt = 0; nt < 4; nt++) {
            const int col = n0 + wn * 32 + nt * 8 + c0;
            float* d = acc[mt][nt];
            if (IS_QK) {
                const float scale = 0.03125f;  // 1/sqrt(1024)
                const int mcol = wn * 32 + nt * 8 + c0;
                const int mk0 = smask[mcol], mk1 = smask[mcol + 1];
                float2 v0, v1;
                v0.x = mk0 ? d[0] * scale : NEG_NUM;
                v0.y = mk1 ? d[1] * scale : NEG_NUM;
                v1.x = mk0 ? d[2] * scale : NEG_NUM;
                v1.y = mk1 ? d[3] * scale : NEG_NUM;
                *(float2*)(Ob + (size_t)row * ldo + col)       = v0;
                *(float2*)(Ob + (size_t)(row + 8) * ldo + col) = v1;
            } else {
                *(float2*)(Ob + (size_t)row * ldo + col)       = make_float2(d[0], d[1]);
                *(float2*)(Ob + (size_t)(row + 8) * ldo + col) = make_float2(d[2], d[3]);
            }
        }
    }
}

// ---------------------------------------------------------------------------
// Convert C -> (Chi, Clo) and transposed (Cthi, Ctlo), tiled 32x32
// ---------------------------------------------------------------------------
__global__ __launch_bounds__(256) void convert_C_kernel(const float* __restrict__ C)
{
    __shared__ float tile[32][33];
    const int b  = blockIdx.z;
    const int s0 = blockIdx.y * 32;
    const int d0 = blockIdx.x * 32;
    const int tx = threadIdx.x;   // 0..15
    const int ty = threadIdx.y;   // 0..15

#pragma unroll
    for (int h = 0; h < 2; h++) {
        int r = ty + h * 16;
        size_t gi = ((size_t)b * Sc + s0 + r) * Dc + d0 + 2 * tx;
        float2 v = *(const float2*)(C + gi);
        tile[r][2 * tx]     = v.x;
        tile[r][2 * tx + 1] = v.y;
        __nv_bfloat162 hh = __floats2bfloat162_rn(v.x, v.y);
        float lx = v.x - __bfloat162float(__low2bfloat16(hh));
        float ly = v.y - __bfloat162float(__high2bfloat16(hh));
        __nv_bfloat162 ll = __floats2bfloat162_rn(lx, ly);
        *(__nv_bfloat162*)(g_Chi + gi) = hh;
        *(__nv_bfloat162*)(g_Clo + gi) = ll;
    }
    __syncthreads();
#pragma unroll
    for (int h = 0; h < 2; h++) {
        int dl = ty + h * 16;
        float a0 = tile[2 * tx][dl];
        float a1 = tile[2 * tx + 1][dl];
        size_t go = ((size_t)b * Dc + d0 + dl) * Sc + s0 + 2 * tx;
        __nv_bfloat162 hh = __floats2bfloat162_rn(a0, a1);
        float lx = a0 - __bfloat162float(__low2bfloat16(hh));
        float ly = a1 - __bfloat162float(__high2bfloat16(hh));
        __nv_bfloat162 ll = __floats2bfloat162_rn(lx, ly);
        *(__nv_bfloat162*)(g_Cthi + go) = hh;
        *(__nv_bfloat162*)(g_Ctlo + go) = ll;
    }
}

// ---------------------------------------------------------------------------
// Convert Q -> (Qhi, Qlo)
// ---------------------------------------------------------------------------
__global__ __launch_bounds__(256) void convert_Q_kernel(const float* __restrict__ Q)
{
    size_t i = ((size_t)blockIdx.x * 256 + threadIdx.x) * 4;
    float4 v = *(const float4*)(Q + i);
    __nv_bfloat162 h01 = __floats2bfloat162_rn(v.x, v.y);
    __nv_bfloat162 h23 = __floats2bfloat162_rn(v.z, v.w);
    __nv_bfloat162 l01 = __floats2bfloat162_rn(v.x - __bfloat162float(__low2bfloat16(h01)),
                                               v.y - __bfloat162float(__high2bfloat16(h01)));
    __nv_bfloat162 l23 = __floats2bfloat162_rn(v.z - __bfloat162float(__low2bfloat16(h23)),
                                               v.w - __bfloat162float(__high2bfloat16(h23)));
    *(__nv_bfloat162*)(g_Qhi + i)     = h01;
    *(__nv_bfloat162*)(g_Qhi + i + 2) = h23;
    *(__nv_bfloat162*)(g_Qlo + i)     = l01;
    *(__nv_bfloat162*)(g_Qlo + i + 2) = l23;
}

// ---------------------------------------------------------------------------
// Softmax over S=4096, in place; emits p fp32 + (Phi, Plo) bf16
// ---------------------------------------------------------------------------
__global__ __launch_bounds__(256) void softmax_kernel(float* __restrict__ P)
{
    const size_t row = blockIdx.x;
    float* p = P + row * Sc;
    const int tid  = threadIdx.x;
    const int warp = tid >> 5;
    const int lane = tid & 31;
    const int base = tid * 16;

    __shared__ float red_max[8];
    __shared__ float red_sum[8];

    float v[16];
#pragma unroll
    for (int i = 0; i < 4; i++) {
        float4 a = *(const float4*)(p + base + i * 4);
        v[i * 4 + 0] = a.x; v[i * 4 + 1] = a.y; v[i * 4 + 2] = a.z; v[i * 4 + 3] = a.w;
    }
    float m = -1e30f;
#pragma unroll
    for (int i = 0; i < 16; i++) m = fmaxf(m, v[i]);
#pragma unroll
    for (int off = 16; off > 0; off >>= 1)
        m = fmaxf(m, __shfl_xor_sync(0xffffffffu, m, off));
    if (lane == 0) red_max[warp] = m;
    __syncthreads();
    float bm = red_max[0];
#pragma unroll
    for (int w = 1; w < 8; w++) bm = fmaxf(bm, red_max[w]);

    float s = 0.0f;
#pragma unroll
    for (int i = 0; i < 16; i++) { v[i] = expf(v[i] - bm); s += v[i]; }
#pragma unroll
    for (int off = 16; off > 0; off >>= 1)
        s += __shfl_xor_sync(0xffffffffu, s, off);
    if (lane == 0) red_sum[warp] = s;
    __syncthreads();
    float tot = 0.0f;
#pragma unroll
    for (int w = 0; w < 8; w++) tot += red_sum[w];
    const float inv = 1.0f / tot;

    __nv_bfloat16* ph = g_Phi + row * Sc + base;
    __nv_bfloat16* pl = g_Plo + row * Sc + base;
#pragma unroll
    for (int i = 0; i < 4; i++) {
        float4 a;
        a.x = v[i * 4 + 0] * inv; a.y = v[i * 4 + 1] * inv;
        a.z = v[i * 4 + 2] * inv; a.w = v[i * 4 + 3] * inv;
        *(float4*)(p + base + i * 4) = a;
        __nv_bfloat162 h01 = __floats2bfloat162_rn(a.x, a.y);
        __nv_bfloat162 h23 = __floats2bfloat162_rn(a.z, a.w);
        __nv_bfloat162 l01 = __floats2bfloat162_rn(a.x - __bfloat162float(__low2bfloat16(h01)),
                                                   a.y - __bfloat162float(__high2bfloat16(h01)));
        __nv_bfloat162 l23 = __floats2bfloat162_rn(a.z - __bfloat162float(__low2bfloat16(h23)),
                                                   a.w - __bfloat162float(__high2bfloat16(h23)));
        *(__nv_bfloat162*)(ph + i * 4)     = h01;
        *(__nv_bfloat162*)(ph + i * 4 + 2) = h23;
        *(__nv_bfloat162*)(pl + i * 4)     = l01;
        *(__nv_bfloat162*)(pl + i * 4 + 2) = l23;
    }
}

// ---------------------------------------------------------------------------
// Launch
// ---------------------------------------------------------------------------
extern "C" void kernel_launch(void* const* d_in, const int* in_sizes, int n_in,
                              void* d_out, int out_size)
{
    const float* ctx   = (const float*)d_in[0];
    const float* query = (const float*)d_in[1];
    const int*   mask  = (const int*)d_in[2];
    float* out = (float*)d_out;

    const size_t BTD = (size_t)Bc * Tc * Dc;
    const size_t BTS = (size_t)Bc * Tc * Sc;

    float* expected_out = out;
    float* p_out;
    if ((size_t)out_size >= BTD + BTS) {
        p_out = out + BTD;
    } else {
        void* sp = nullptr;
        cudaGetSymbolAddress(&sp, g_p_scratch);
        p_out = (float*)sp;
    }

    void *pChi, *pClo, *pCthi, *pCtlo, *pQhi, *pQlo, *pPhi, *pPlo;
    cudaGetSymbolAddress(&pChi,  g_Chi);
    cudaGetSymbolAddress(&pClo,  g_Clo);
    cudaGetSymbolAddress(&pCthi, g_Cthi);
    cudaGetSymbolAddress(&pCtlo, g_Ctlo);
    cudaGetSymbolAddress(&pQhi,  g_Qhi);
    cudaGetSymbolAddress(&pQlo,  g_Qlo);
    cudaGetSymbolAddress(&pPhi,  g_Phi);
    cudaGetSymbolAddress(&pPlo,  g_Plo);

    cudaFuncSetAttribute(gemm_hmma<Dc, true>,  cudaFuncAttributeMaxDynamicSharedMemorySize, SMEM_TOTAL);
    cudaFuncSetAttribute(gemm_hmma<Sc, false>, cudaFuncAttributeMaxDynamicSharedMemorySize, SMEM_TOTAL);

    // 1. Converts
    convert_C_kernel<<<dim3(Dc / 32, Sc / 32, Bc), dim3(16, 16)>>>(ctx);
    convert_Q_kernel<<<(unsigned)(BTD / 4 / 256), 256>>>(query);

    // 2. QK^T -> masked scaled scores into p buffer
    gemm_hmma<Dc, true><<<dim3(Sc / 128, Tc / 128, Bc), 256, SMEM_TOTAL>>>(
        (const __nv_bfloat16*)pQhi, (const __nv_bfloat16*)pQlo,
        (const __nv_bfloat16*)pChi, (const __nv_bfloat16*)pClo,
        mask, p_out, Dc, Dc, Sc, (size_t)Tc * Dc, (size_t)Sc * Dc, (size_t)Tc * Sc);

    // 3. Softmax (fused bf16 hi/lo emit of P)
    softmax_kernel<<<Bc * Tc, 256>>>(p_out);

    // 4. P @ C^T(stored K-major) -> expected_ctx
    gemm_hmma<Sc, false><<<dim3(Dc / 128, Tc / 128, Bc), 256, SMEM_TOTAL>>>(
        (const __nv_bfloat16*)pPhi, (const __nv_bfloat16*)pPlo,
        (const __nv_bfloat16*)pCthi, (const __nv_bfloat16*)pCtlo,
        nullptr, expected_out, Sc, Sc, Dc, (size_t)Tc * Sc, (size_t)Dc * Sc, (size_t)Tc * Dc);
}